// round 1
// baseline (speedup 1.0000x reference)
#include <cuda_runtime.h>
#include <cuda_bf16.h>
#include <cstdint>

// Problem constants
#define N_NODES 50000
#define N_EDGES 1600000
#define IN_DIM  512
#define OUT_DIM 256

// Scratch: support = inputs @ weight, [N_NODES, OUT_DIM] fp32 (51.2 MB)
__device__ static float g_support[(size_t)N_NODES * OUT_DIM];

// ---------------------------------------------------------------------------
// Tiled FP32 GEMM: C[M,N] = A[M,K] @ B[K,N]
// M=50000, K=512, N=256. BM=64, BN=64, BK=16, 256 threads, 4x4 microtile.
// ---------------------------------------------------------------------------
#define BM 64
#define BN 64
#define BK 16
#define TM 4
#define TN 4

__global__ __launch_bounds__(256) void sgemm_kernel(
    const float* __restrict__ A,   // [M, K]
    const float* __restrict__ B,   // [K, N]
    float* __restrict__ C)         // [M, N]
{
    const int M = N_NODES, K = IN_DIM, N = OUT_DIM;

    __shared__ float As[BK][BM];      // transposed A tile
    __shared__ float Bs[BK][BN];

    const int tid = threadIdx.x;
    const int block_row = blockIdx.y * BM;
    const int block_col = blockIdx.x * BN;

    // compute-thread microtile coords (16x16 thread grid)
    const int tr = (tid >> 4) * TM;   // 0..60
    const int tc = (tid & 15) * TN;   // 0..60

    // A-tile load coords: 64x16 floats = 256 float4, one per thread
    const int a_row = tid >> 2;          // 0..63
    const int a_col = (tid & 3) * 4;     // 0,4,8,12
    // B-tile load coords: 16x64 floats = 256 float4
    const int b_row = tid >> 4;          // 0..15
    const int b_col = (tid & 15) * 4;    // 0..60

    float acc[TM][TN];
#pragma unroll
    for (int i = 0; i < TM; i++)
#pragma unroll
        for (int j = 0; j < TN; j++) acc[i][j] = 0.0f;

    const int grow = block_row + a_row;
    const bool a_ok = (grow < M);

    for (int k0 = 0; k0 < K; k0 += BK) {
        float4 av = make_float4(0.f, 0.f, 0.f, 0.f);
        if (a_ok)
            av = *reinterpret_cast<const float4*>(&A[(size_t)grow * K + k0 + a_col]);
        // transposed store into As
        As[a_col + 0][a_row] = av.x;
        As[a_col + 1][a_row] = av.y;
        As[a_col + 2][a_row] = av.z;
        As[a_col + 3][a_row] = av.w;

        float4 bv = *reinterpret_cast<const float4*>(
            &B[(size_t)(k0 + b_row) * N + block_col + b_col]);
        *reinterpret_cast<float4*>(&Bs[b_row][b_col]) = bv;

        __syncthreads();

#pragma unroll
        for (int k = 0; k < BK; k++) {
            float4 a4 = *reinterpret_cast<const float4*>(&As[k][tr]);
            float4 b4 = *reinterpret_cast<const float4*>(&Bs[k][tc]);
            float ar[TM] = {a4.x, a4.y, a4.z, a4.w};
            float br[TN] = {b4.x, b4.y, b4.z, b4.w};
#pragma unroll
            for (int i = 0; i < TM; i++)
#pragma unroll
                for (int j = 0; j < TN; j++)
                    acc[i][j] = fmaf(ar[i], br[j], acc[i][j]);
        }
        __syncthreads();
    }

    // store
#pragma unroll
    for (int i = 0; i < TM; i++) {
        int r = block_row + tr + i;
        if (r < M) {
            float4 v = make_float4(acc[i][0], acc[i][1], acc[i][2], acc[i][3]);
            *reinterpret_cast<float4*>(&C[(size_t)r * N + block_col + tc]) = v;
        }
    }
}

// ---------------------------------------------------------------------------
// Init output: out[n, j] = bias[j]
// ---------------------------------------------------------------------------
__global__ __launch_bounds__(256) void init_out_kernel(
    float* __restrict__ out, const float* __restrict__ bias)
{
    __shared__ float sb[OUT_DIM];
    sb[threadIdx.x] = bias[threadIdx.x];   // blockDim.x == 256 == OUT_DIM
    __syncthreads();
    // each block writes some rows; grid-stride over rows
    for (int row = blockIdx.x; row < N_NODES; row += gridDim.x) {
        out[(size_t)row * OUT_DIM + threadIdx.x] = sb[threadIdx.x];
    }
}

// ---------------------------------------------------------------------------
// SpMM scatter: out[r] += val * support[c]  per edge.
// One warp per edge: 256 floats = 64 float4 = 32 lanes x 2 float4.
// Vector reduction: red.global.add.v4.f32 (sm_90+).
// ---------------------------------------------------------------------------
__global__ __launch_bounds__(256) void spmm_kernel(
    const int* __restrict__ rows,
    const int* __restrict__ cols,
    const float* __restrict__ vals,
    float* __restrict__ out)
{
    const int warp = threadIdx.x >> 5;
    const int lane = threadIdx.x & 31;
    const int e = blockIdx.x * 8 + warp;
    if (e >= N_EDGES) return;

    const int r = rows[e];
    const int c = cols[e];
    const float v = vals[e];

    const float4* __restrict__ src =
        reinterpret_cast<const float4*>(g_support + (size_t)c * OUT_DIM);
    float4* dst = reinterpret_cast<float4*>(out + (size_t)r * OUT_DIM);

#pragma unroll
    for (int i = 0; i < 2; i++) {
        float4 x = __ldg(&src[lane + 32 * i]);
        x.x *= v; x.y *= v; x.z *= v; x.w *= v;
        asm volatile(
            "red.global.add.v4.f32 [%0], {%1, %2, %3, %4};"
            :: "l"(dst + lane + 32 * i),
               "f"(x.x), "f"(x.y), "f"(x.z), "f"(x.w)
            : "memory");
    }
}

// ---------------------------------------------------------------------------
// Launch
// ---------------------------------------------------------------------------
extern "C" void kernel_launch(void* const* d_in, const int* in_sizes, int n_in,
                              void* d_out, int out_size)
{
    const float* inputs   = (const float*)d_in[0];   // [N_NODES, IN_DIM]
    const int*   edge_row = (const int*)  d_in[1];   // [N_EDGES]
    const int*   edge_col = (const int*)  d_in[2];   // [N_EDGES]
    const float* edge_val = (const float*)d_in[3];   // [N_EDGES]
    const float* weight   = (const float*)d_in[4];   // [IN_DIM, OUT_DIM]
    const float* bias     = (const float*)d_in[5];   // [OUT_DIM]
    float* out = (float*)d_out;                      // [N_NODES, OUT_DIM]

    float* support = nullptr;
    cudaGetSymbolAddress((void**)&support, g_support);

    // 1) support = inputs @ weight
    {
        dim3 grid(OUT_DIM / BN, (N_NODES + BM - 1) / BM);
        sgemm_kernel<<<grid, 256>>>(inputs, weight, support);
    }

    // 2) out = bias (broadcast)
    {
        init_out_kernel<<<2048, OUT_DIM>>>(out, bias);
    }

    // 3) scatter: out[r] += val * support[c]
    {
        int blocks = (N_EDGES + 7) / 8;
        spmm_kernel<<<blocks, 256>>>(edge_row, edge_col, edge_val, out);
    }
}

// round 3
// speedup vs baseline: 1.3412x; 1.3412x over previous
#include <cuda_runtime.h>
#include <cuda_bf16.h>
#include <mma.h>
#include <cstdint>

using namespace nvcuda;

// Problem constants
#define N_NODES 50000
#define N_EDGES 1600000
#define IN_DIM  512
#define OUT_DIM 256

// Scratch: support = inputs @ weight, [N_NODES, OUT_DIM] fp32 (51.2 MB)
__device__ static float g_support[(size_t)N_NODES * OUT_DIM];

// Pre-converted B (weight) in bf16 hi/lo split, padded rows for alignment.
#define B_LDM 272   // 256 + 16 pad; row stride 544B (32B-aligned)
__device__ static __nv_bfloat16 g_Bh[(size_t)IN_DIM * B_LDM];
__device__ static __nv_bfloat16 g_Bl[(size_t)IN_DIM * B_LDM];

// ---------------------------------------------------------------------------
// B pre-convert: f32 -> bf16 hi + bf16 lo. One block per k-row.
// ---------------------------------------------------------------------------
__global__ __launch_bounds__(256) void convert_B_kernel(const float* __restrict__ B)
{
    const int k = blockIdx.x;        // 0..511
    const int n = threadIdx.x;       // 0..255
    const float x = B[(size_t)k * OUT_DIM + n];
    const __nv_bfloat16 h = __float2bfloat16_rn(x);
    const __nv_bfloat16 l = __float2bfloat16_rn(x - __bfloat162float(h));
    g_Bh[(size_t)k * B_LDM + n] = h;
    g_Bl[(size_t)k * B_LDM + n] = l;
    if (n < B_LDM - OUT_DIM) {       // zero the pad
        g_Bh[(size_t)k * B_LDM + OUT_DIM + n] = __float2bfloat16_rn(0.f);
        g_Bl[(size_t)k * B_LDM + OUT_DIM + n] = __float2bfloat16_rn(0.f);
    }
}

// ---------------------------------------------------------------------------
// GEMM: C[M=50000,256] = A[M,512] @ B[512,256] via WMMA bf16 3-term split.
// CTA: 128 rows x 256 cols, 512 threads (16 warps, 4x4), warp tile 32x64.
// K processed in 4 chunks of 128; A converted f32->bf16 hi/lo into smem.
// B fragments loaded directly from pre-converted global (L1-resident).
// ---------------------------------------------------------------------------
#define GM_BM   128
#define GM_KC   128
#define A_LDM   144     // 128 + 16 pad; row stride 288B (32B-aligned)
#define GM_SMEM (2 * GM_BM * A_LDM * 2)   // Ah + Al = 73728 B

__global__ __launch_bounds__(512, 1) void gemm_wmma_split_kernel(
    const float* __restrict__ A,   // [M, 512]
    float* __restrict__ C)         // [M, 256]
{
    extern __shared__ __align__(32) char smem[];
    __nv_bfloat16* Ah = reinterpret_cast<__nv_bfloat16*>(smem);
    __nv_bfloat16* Al = Ah + GM_BM * A_LDM;

    const int tid  = threadIdx.x;
    const int wid  = tid >> 5;
    const int wm   = wid >> 2;           // 0..3: warp row block (32 rows)
    const int wn   = wid & 3;            // 0..3: warp col block (64 cols)
    const int mbase = blockIdx.x * GM_BM;

    wmma::fragment<wmma::accumulator, 16, 16, 16, float> acc[2][4];
#pragma unroll
    for (int i = 0; i < 2; i++)
#pragma unroll
        for (int j = 0; j < 4; j++) wmma::fill_fragment(acc[i][j], 0.0f);

    for (int ch = 0; ch < IN_DIM / GM_KC; ch++) {
        // ---- load + convert A chunk: 128 rows x 128 k-cols ----
        // 4096 float4 total, 8 per thread.
#pragma unroll
        for (int it = 0; it < 8; it++) {
            const int idx = tid + 512 * it;
            const int row = idx >> 5;          // 0..127
            const int f4  = idx & 31;          // 0..31 (float4 col)
            const int g   = mbase + row;
            float4 v = make_float4(0.f, 0.f, 0.f, 0.f);
            if (g < N_NODES)
                v = *reinterpret_cast<const float4*>(
                    &A[(size_t)g * IN_DIM + ch * GM_KC + f4 * 4]);

            __nv_bfloat16 h0 = __float2bfloat16_rn(v.x);
            __nv_bfloat16 h1 = __float2bfloat16_rn(v.y);
            __nv_bfloat16 h2 = __float2bfloat16_rn(v.z);
            __nv_bfloat16 h3 = __float2bfloat16_rn(v.w);
            __nv_bfloat16 l0 = __float2bfloat16_rn(v.x - __bfloat162float(h0));
            __nv_bfloat16 l1 = __float2bfloat16_rn(v.y - __bfloat162float(h1));
            __nv_bfloat16 l2 = __float2bfloat16_rn(v.z - __bfloat162float(h2));
            __nv_bfloat16 l3 = __float2bfloat16_rn(v.w - __bfloat162float(h3));

            uint2 hp, lp;
            hp.x = (uint32_t)__bfloat16_as_ushort(h0) |
                   ((uint32_t)__bfloat16_as_ushort(h1) << 16);
            hp.y = (uint32_t)__bfloat16_as_ushort(h2) |
                   ((uint32_t)__bfloat16_as_ushort(h3) << 16);
            lp.x = (uint32_t)__bfloat16_as_ushort(l0) |
                   ((uint32_t)__bfloat16_as_ushort(l1) << 16);
            lp.y = (uint32_t)__bfloat16_as_ushort(l2) |
                   ((uint32_t)__bfloat16_as_ushort(l3) << 16);

            const int e = row * A_LDM + f4 * 4;   // element offset
            *reinterpret_cast<uint2*>(Ah + e) = hp;
            *reinterpret_cast<uint2*>(Al + e) = lp;
        }
        __syncthreads();

        // ---- compute: 8 k-steps of 16 ----
#pragma unroll
        for (int ks = 0; ks < GM_KC / 16; ks++) {
            wmma::fragment<wmma::matrix_a, 16, 16, 16, __nv_bfloat16, wmma::row_major> ah[2], al[2];
#pragma unroll
            for (int i = 0; i < 2; i++) {
                const int ar = wm * 32 + i * 16;
                wmma::load_matrix_sync(ah[i], Ah + ar * A_LDM + ks * 16, A_LDM);
                wmma::load_matrix_sync(al[i], Al + ar * A_LDM + ks * 16, A_LDM);
            }
            const int krow = ch * GM_KC + ks * 16;
#pragma unroll
            for (int j = 0; j < 4; j++) {
                const int nc = wn * 64 + j * 16;
                wmma::fragment<wmma::matrix_b, 16, 16, 16, __nv_bfloat16, wmma::row_major> bh, bl;
                wmma::load_matrix_sync(bh, g_Bh + (size_t)krow * B_LDM + nc, B_LDM);
                wmma::load_matrix_sync(bl, g_Bl + (size_t)krow * B_LDM + nc, B_LDM);
#pragma unroll
                for (int i = 0; i < 2; i++) {
                    wmma::mma_sync(acc[i][j], ah[i], bh, acc[i][j]);
                    wmma::mma_sync(acc[i][j], ah[i], bl, acc[i][j]);
                    wmma::mma_sync(acc[i][j], al[i], bh, acc[i][j]);
                }
            }
        }
        __syncthreads();
    }

    // ---- store: frag rows are multiples of 16; N_NODES % 16 == 0, so each
    //      fragment is fully in range or fully out. ----
#pragma unroll
    for (int i = 0; i < 2; i++) {
        const int r0 = mbase + wm * 32 + i * 16;
        if (r0 + 16 <= N_NODES) {
#pragma unroll
            for (int j = 0; j < 4; j++) {
                const int c0 = wn * 64 + j * 16;
                wmma::store_matrix_sync(&C[(size_t)r0 * OUT_DIM + c0],
                                        acc[i][j], OUT_DIM, wmma::mem_row_major);
            }
        }
    }
}

// ---------------------------------------------------------------------------
// Init output: out[n, j] = bias[j]
// ---------------------------------------------------------------------------
__global__ __launch_bounds__(256) void init_out_kernel(
    float* __restrict__ out, const float* __restrict__ bias)
{
    __shared__ float sb[OUT_DIM];
    sb[threadIdx.x] = bias[threadIdx.x];
    __syncthreads();
    for (int row = blockIdx.x; row < N_NODES; row += gridDim.x) {
        out[(size_t)row * OUT_DIM + threadIdx.x] = sb[threadIdx.x];
    }
}

// ---------------------------------------------------------------------------
// SpMM scatter: out[r] += val * support[c] per edge. One warp per edge.
// red.global.add.v4.f32 (sm_90+ base feature).
// ---------------------------------------------------------------------------
__global__ __launch_bounds__(256) void spmm_kernel(
    const int* __restrict__ rows,
    const int* __restrict__ cols,
    const float* __restrict__ vals,
    float* __restrict__ out)
{
    const int warp = threadIdx.x >> 5;
    const int lane = threadIdx.x & 31;
    const int e = blockIdx.x * 8 + warp;
    if (e >= N_EDGES) return;

    const int r = rows[e];
    const int c = cols[e];
    const float v = vals[e];

    const float4* __restrict__ src =
        reinterpret_cast<const float4*>(g_support + (size_t)c * OUT_DIM);
    float4* dst = reinterpret_cast<float4*>(out + (size_t)r * OUT_DIM);

#pragma unroll
    for (int i = 0; i < 2; i++) {
        float4 x = __ldg(&src[lane + 32 * i]);
        x.x *= v; x.y *= v; x.z *= v; x.w *= v;
        asm volatile(
            "red.global.add.v4.f32 [%0], {%1, %2, %3, %4};"
            :: "l"(dst + lane + 32 * i),
               "f"(x.x), "f"(x.y), "f"(x.z), "f"(x.w)
            : "memory");
    }
}

// ---------------------------------------------------------------------------
// Launch
// ---------------------------------------------------------------------------
extern "C" void kernel_launch(void* const* d_in, const int* in_sizes, int n_in,
                              void* d_out, int out_size)
{
    const float* inputs   = (const float*)d_in[0];   // [N_NODES, IN_DIM]
    const int*   edge_row = (const int*)  d_in[1];   // [N_EDGES]
    const int*   edge_col = (const int*)  d_in[2];   // [N_EDGES]
    const float* edge_val = (const float*)d_in[3];   // [N_EDGES]
    const float* weight   = (const float*)d_in[4];   // [IN_DIM, OUT_DIM]
    const float* bias     = (const float*)d_in[5];   // [OUT_DIM]
    float* out = (float*)d_out;                      // [N_NODES, OUT_DIM]

    float* support = nullptr;
    cudaGetSymbolAddress((void**)&support, g_support);

    // 0) B -> bf16 hi/lo split (tiny: 512KB read)
    convert_B_kernel<<<IN_DIM, 256>>>(weight);

    // 1) support = inputs @ weight  (WMMA bf16 3-split)
    {
        static int smem_set = 0;
        if (!smem_set) {
            cudaFuncSetAttribute(gemm_wmma_split_kernel,
                                 cudaFuncAttributeMaxDynamicSharedMemorySize, GM_SMEM);
            smem_set = 1;
        }
        int grid = (N_NODES + GM_BM - 1) / GM_BM;   // 391
        gemm_wmma_split_kernel<<<grid, 512, GM_SMEM>>>(inputs, support);
    }

    // 2) out = bias (broadcast)
    init_out_kernel<<<2048, OUT_DIM>>>(out, bias);

    // 3) scatter: out[r] += val * support[c]
    {
        int blocks = (N_EDGES + 7) / 8;
        spmm_kernel<<<blocks, 256>>>(edge_row, edge_col, edge_val, out);
    }
}